// round 12
// baseline (speedup 1.0000x reference)
#include <cuda_runtime.h>
#include <cuda_fp16.h>
#include <cuda_bf16.h>

#define DPAR   1024
#define KSEL   32
#define NITER  4
#define CHUNKS 8          // 8 x float4 per lane = 32 elements/lane
#define H2N    16         // 16 half2 = 32 z values per lane
#define WPB    8          // warps (rows) per block

__device__ __align__(16) float g_invstd[DPAR];
__device__ __align__(16) float g_nmi[DPAR];      // -mean * invstd
__device__ float g_alpha;
__device__ float g_sigma;

__global__ void prep_kernel(const float* __restrict__ ema_mean,
                            const float* __restrict__ ema_sq,
                            const float* __restrict__ log_alpha,
                            const float* __restrict__ log_sigma, int d) {
    int i = blockIdx.x * blockDim.x + threadIdx.x;
    if (i < d) {
        float m = ema_mean[i];
        float v = ema_sq[i] - m * m;
        v = fmaxf(v, 1e-6f);
        float iv = rsqrtf(v);
        g_invstd[i] = iv;
        g_nmi[i]    = -m * iv;
    }
    if (i == 0) {
        g_alpha = expf(log_alpha[0]);
        g_sigma = expf(log_sigma[0]);
    }
}

// Phi(x) = 0.5*(1+erf(x/sqrt2)) via A&S 7.1.25 3-term erfc (|eps|<=2.5e-5),
// 0.5 and 1/sqrt2 folded into coefficients.  gelu(x) = x * Phi(x).
__device__ __forceinline__ float gelu_phi(float x) {
    float ax = fabsf(x);
    // t = 1 / (1 + 0.47047 * |x| / sqrt2)
    float t  = __fdividef(1.0f, fmaf(0.332670553f, ax, 1.0f));
    // 0.5*(a1 t + a2 t^2 + a3 t^3)
    float P  = t * fmaf(t, fmaf(t, 0.3739278f, -0.0479399f), 0.1740121f);
    // exp(-x^2/2) = exp2(-0.72134752 * x^2)
    float e  = exp2f(x * x * -0.72134752f);
    float he = P * e;                      // 0.5*erfc(|x|/sqrt2)
    // phi = 0.5 + copysign(0.5 - he, x)   (0.5 - he >= 0)
    return 0.5f + copysignf(0.5f - he, x);
}

__global__ __launch_bounds__(256, 6) void gelu_topk_kernel(
        const float4* __restrict__ x4, float4* __restrict__ out4, int rows) {
    __shared__ float4 sx[WPB * 256];                    // 32 KB: x staged on-chip
    int wib  = threadIdx.x >> 5;                        // warp in block
    int gw   = blockIdx.x * WPB + wib;                  // one warp per row
    int lane = threadIdx.x & 31;
    if (gw >= rows) return;

    const float4* xr   = x4   + (size_t)gw * (DPAR / 4) + lane;
    float4*       orow = out4 + (size_t)gw * (DPAR / 4) + lane;
    const float4* s4 = reinterpret_cast<const float4*>(g_invstd) + lane;
    const float4* n4 = reinterpret_cast<const float4*>(g_nmi)    + lane;
    float4* swarp = sx + wib * 256 + lane;              // this thread's slots

    // ---- pass 1: z = |x*iv + nmi| (fp32) -> half2; stage x in smem ----
    __half2 z2[H2N];
    __half2 tmaxA = __float2half2_rn(0.0f);
    __half2 tmaxB = __float2half2_rn(0.0f);
    #pragma unroll
    for (int c = 0; c < CHUNKS; c++) {
        float4 xv = __ldg(xr + c * 32);
        swarp[c * 32] = xv;                             // deterministic reuse
        float4 iv = __ldg(s4 + c * 32);
        float4 nm = __ldg(n4 + c * 32);
        float a  = fabsf(fmaf(xv.x, iv.x, nm.x));
        float b  = fabsf(fmaf(xv.y, iv.y, nm.y));
        float cc = fabsf(fmaf(xv.z, iv.z, nm.z));
        float dd = fabsf(fmaf(xv.w, iv.w, nm.w));
        z2[c * 2 + 0] = __floats2half2_rn(a, b);
        z2[c * 2 + 1] = __floats2half2_rn(cc, dd);
        tmaxA = __hmax2(tmaxA, z2[c * 2 + 0]);
        tmaxB = __hmax2(tmaxB, z2[c * 2 + 1]);
    }
    __half2 tmax2 = __hmax2(tmaxA, tmaxB);
    float tmax = fmaxf(__low2float(tmax2), __high2float(tmax2));

    // ---- bracket the K-th largest via REDUX on bit patterns (z >= 0) ----
    //      lo = min over lanes of per-lane max; hi = row max
    unsigned tb = __float_as_uint(tmax);
    float hi = __uint_as_float(__reduce_max_sync(0xffffffffu, tb));
    float lo = __uint_as_float(__reduce_min_sync(0xffffffffu, tb));
    float c_lo = 1024.0f, c_hi = 0.0f;    // counts at bracket ends

    // ---- count-based bisection, packed half2 compares + REDUX.SUM ----
    #pragma unroll
    for (int it = 0; it < NITER; ++it) {
        float T = 0.5f * (lo + hi);
        __half2 T2 = __float2half2_rn(T);
        __half2 a0 = __float2half2_rn(0.0f), a1 = a0, a2 = a0, a3 = a0;
        #pragma unroll
        for (int i = 0; i < H2N; i += 4) {
            a0 = __hadd2(a0, __hgt2(z2[i + 0], T2));
            a1 = __hadd2(a1, __hgt2(z2[i + 1], T2));
            a2 = __hadd2(a2, __hgt2(z2[i + 2], T2));
            a3 = __hadd2(a3, __hgt2(z2[i + 3], T2));
        }
        __half2 acc = __hadd2(__hadd2(a0, a1), __hadd2(a2, a3));
        int cnt = (int)(__low2float(acc) + __high2float(acc));
        cnt = __reduce_add_sync(0xffffffffu, cnt);
        if (cnt >= KSEL) { lo = T; c_lo = (float)cnt; }
        else             { hi = T; c_hi = (float)cnt; }
    }

    // ---- top-K sum: exact part above hi (count = c_hi, already known) ----
    {
        __half2 hi2 = __float2half2_rn(hi);
        __half2 s0 = __float2half2_rn(0.0f), s1 = s0, s2 = s0, s3 = s0;
        #pragma unroll
        for (int i = 0; i < H2N; i += 4) {
            s0 = __hfma2(__hgt2(z2[i + 0], hi2), z2[i + 0], s0);
            s1 = __hfma2(__hgt2(z2[i + 1], hi2), z2[i + 1], s1);
            s2 = __hfma2(__hgt2(z2[i + 2], hi2), z2[i + 2], s2);
            s3 = __hfma2(__hgt2(z2[i + 3], hi2), z2[i + 3], s3);
        }
        __half2 sacc = __hadd2(__hadd2(s0, s1), __hadd2(s2, s3));
        float ssum = __low2float(sacc) + __high2float(sacc);
        // fixed-point warp sum: one REDUX instead of 5 shfl+add
        int ssi = (int)(ssum * 1024.0f);
        ssi = __reduce_add_sync(0xffffffffu, ssi);
        ssum = (float)ssi * (1.0f / 1024.0f);
        float chi = c_hi;                 // exact count of z > hi (bisection invariant)

        // false-position estimate of the K-th order statistic inside [lo,hi]
        float Tk = lo + (hi - lo) * (c_lo - (float)KSEL)
                        * __fdividef(1.0f, fmaxf(c_lo - c_hi, 1.0f));
        Tk = fminf(fmaxf(Tk, lo), hi);

        float surp = (ssum + ((float)KSEL - chi) * Tk) * (1.0f / (float)KSEL);
        float gate = 1.0f + g_alpha * tanhf(g_sigma * surp);

        // ---- pass 2: GELU(x) * gate, x re-read from SMEM (no DRAM) ----
        #pragma unroll
        for (int c = 0; c < CHUNKS; c++) {
            float4 xv = swarp[c * 32];
            float4 o;
            o.x = (gate * xv.x) * gelu_phi(xv.x);
            o.y = (gate * xv.y) * gelu_phi(xv.y);
            o.z = (gate * xv.z) * gelu_phi(xv.z);
            o.w = (gate * xv.w) * gelu_phi(xv.w);
            orow[c * 32] = o;
        }
    }
}

extern "C" void kernel_launch(void* const* d_in, const int* in_sizes, int n_in,
                              void* d_out, int out_size) {
    const float* x         = (const float*)d_in[0];
    const float* log_alpha = (const float*)d_in[1];
    const float* log_sigma = (const float*)d_in[2];
    const float* ema_mean  = (const float*)d_in[3];
    const float* ema_sq    = (const float*)d_in[4];
    float* out = (float*)d_out;

    int d    = in_sizes[3];          // 1024
    int rows = in_sizes[0] / d;      // 32768

    prep_kernel<<<(d + 255) / 256, 256>>>(ema_mean, ema_sq, log_alpha, log_sigma, d);

    int blocks = (rows + WPB - 1) / WPB;    // 8 warps (rows) per 256-thread block
    gelu_topk_kernel<<<blocks, 256>>>(
        reinterpret_cast<const float4*>(x),
        reinterpret_cast<float4*>(out), rows);
}

// round 13
// speedup vs baseline: 1.0406x; 1.0406x over previous
#include <cuda_runtime.h>
#include <cuda_fp16.h>
#include <cuda_bf16.h>

#define DPAR   1024
#define KSEL   32
#define NITER  4
#define CHUNKS 8          // 8 x float4 per lane = 32 elements/lane
#define H2N    16         // 16 half2 = 32 z values per lane
#define WPB    8          // warps (rows) per block

__device__ __align__(16) float g_invstd[DPAR];
__device__ __align__(16) float g_nmi[DPAR];      // -mean * invstd
__device__ float g_alpha;
__device__ float g_sigma;

__global__ void prep_kernel(const float* __restrict__ ema_mean,
                            const float* __restrict__ ema_sq,
                            const float* __restrict__ log_alpha,
                            const float* __restrict__ log_sigma, int d) {
    int i = blockIdx.x * blockDim.x + threadIdx.x;
    if (i < d) {
        float m = ema_mean[i];
        float v = ema_sq[i] - m * m;
        v = fmaxf(v, 1e-6f);
        float iv = rsqrtf(v);
        g_invstd[i] = iv;
        g_nmi[i]    = -m * iv;
    }
    if (i == 0) {
        g_alpha = expf(log_alpha[0]);
        g_sigma = expf(log_sigma[0]);
    }
}

// Phi(x) = 0.5*(1+erf(x/sqrt2)) via A&S 7.1.25 3-term erfc (|eps|<=2.5e-5),
// 0.5 and 1/sqrt2 folded into coefficients.  gelu(x) = x * Phi(x).
__device__ __forceinline__ float gelu_phi(float x) {
    float ax = fabsf(x);
    // t = 1 / (1 + 0.47047 * |x| / sqrt2)
    float t  = __fdividef(1.0f, fmaf(0.332670553f, ax, 1.0f));
    // 0.5*(a1 t + a2 t^2 + a3 t^3)
    float P  = t * fmaf(t, fmaf(t, 0.3739278f, -0.0479399f), 0.1740121f);
    // exp(-x^2/2) = exp2(-0.72134752 * x^2)
    float e  = exp2f(x * x * -0.72134752f);
    float he = P * e;                      // 0.5*erfc(|x|/sqrt2)
    // phi = 0.5 + copysign(0.5 - he, x)   (0.5 - he >= 0)
    return 0.5f + copysignf(0.5f - he, x);
}

__global__ __launch_bounds__(256, 6) void gelu_topk_kernel(
        const float4* __restrict__ x4, float4* __restrict__ out4, int rows) {
    __shared__ float4 sg[WPB * 256];                    // 32 KB: ungated GELU(x)
    int wib  = threadIdx.x >> 5;                        // warp in block
    int gw   = blockIdx.x * WPB + wib;                  // one warp per row
    int lane = threadIdx.x & 31;
    if (gw >= rows) return;

    const float4* xr   = x4   + (size_t)gw * (DPAR / 4) + lane;
    float4*       orow = out4 + (size_t)gw * (DPAR / 4) + lane;
    const float4* s4 = reinterpret_cast<const float4*>(g_invstd) + lane;
    const float4* n4 = reinterpret_cast<const float4*>(g_nmi)    + lane;
    float4* swarp = sg + wib * 256 + lane;              // this thread's slots

    // ---- pass 1: z = |x*iv + nmi| -> half2;  gelu(x) -> smem (overlapped
    //      with the DRAM load latency, so the post-bisection tail is tiny) ----
    __half2 z2[H2N];
    __half2 tmaxA = __float2half2_rn(0.0f);
    __half2 tmaxB = __float2half2_rn(0.0f);
    #pragma unroll
    for (int c = 0; c < CHUNKS; c++) {
        float4 xv = __ldg(xr + c * 32);
        float4 iv = __ldg(s4 + c * 32);
        float4 nm = __ldg(n4 + c * 32);
        float a  = fabsf(fmaf(xv.x, iv.x, nm.x));
        float b  = fabsf(fmaf(xv.y, iv.y, nm.y));
        float cc = fabsf(fmaf(xv.z, iv.z, nm.z));
        float dd = fabsf(fmaf(xv.w, iv.w, nm.w));
        z2[c * 2 + 0] = __floats2half2_rn(a, b);
        z2[c * 2 + 1] = __floats2half2_rn(cc, dd);
        tmaxA = __hmax2(tmaxA, z2[c * 2 + 0]);
        tmaxB = __hmax2(tmaxB, z2[c * 2 + 1]);
        float4 g;                                       // ungated GELU(x)
        g.x = xv.x * gelu_phi(xv.x);
        g.y = xv.y * gelu_phi(xv.y);
        g.z = xv.z * gelu_phi(xv.z);
        g.w = xv.w * gelu_phi(xv.w);
        swarp[c * 32] = g;
    }
    __half2 tmax2 = __hmax2(tmaxA, tmaxB);
    float tmax = fmaxf(__low2float(tmax2), __high2float(tmax2));

    // ---- bracket the K-th largest via REDUX on bit patterns (z >= 0) ----
    //      lo = min over lanes of per-lane max; hi = row max
    unsigned tb = __float_as_uint(tmax);
    float hi = __uint_as_float(__reduce_max_sync(0xffffffffu, tb));
    float lo = __uint_as_float(__reduce_min_sync(0xffffffffu, tb));
    float c_lo = 1024.0f, c_hi = 0.0f;    // counts at bracket ends

    // ---- count-based bisection, packed half2 compares + REDUX.SUM ----
    #pragma unroll
    for (int it = 0; it < NITER; ++it) {
        float T = 0.5f * (lo + hi);
        __half2 T2 = __float2half2_rn(T);
        __half2 a0 = __float2half2_rn(0.0f), a1 = a0, a2 = a0, a3 = a0;
        #pragma unroll
        for (int i = 0; i < H2N; i += 4) {
            a0 = __hadd2(a0, __hgt2(z2[i + 0], T2));
            a1 = __hadd2(a1, __hgt2(z2[i + 1], T2));
            a2 = __hadd2(a2, __hgt2(z2[i + 2], T2));
            a3 = __hadd2(a3, __hgt2(z2[i + 3], T2));
        }
        __half2 acc = __hadd2(__hadd2(a0, a1), __hadd2(a2, a3));
        int cnt = (int)(__low2float(acc) + __high2float(acc));
        cnt = __reduce_add_sync(0xffffffffu, cnt);
        if (cnt >= KSEL) { lo = T; c_lo = (float)cnt; }
        else             { hi = T; c_hi = (float)cnt; }
    }

    // ---- top-K sum: exact part above hi (count = c_hi, already known) ----
    {
        __half2 hi2 = __float2half2_rn(hi);
        __half2 s0 = __float2half2_rn(0.0f), s1 = s0, s2 = s0, s3 = s0;
        #pragma unroll
        for (int i = 0; i < H2N; i += 4) {
            s0 = __hfma2(__hgt2(z2[i + 0], hi2), z2[i + 0], s0);
            s1 = __hfma2(__hgt2(z2[i + 1], hi2), z2[i + 1], s1);
            s2 = __hfma2(__hgt2(z2[i + 2], hi2), z2[i + 2], s2);
            s3 = __hfma2(__hgt2(z2[i + 3], hi2), z2[i + 3], s3);
        }
        __half2 sacc = __hadd2(__hadd2(s0, s1), __hadd2(s2, s3));
        float ssum = __low2float(sacc) + __high2float(sacc);
        // fixed-point warp sum: one REDUX instead of 5 shfl+add
        int ssi = (int)(ssum * 1024.0f);
        ssi = __reduce_add_sync(0xffffffffu, ssi);
        ssum = (float)ssi * (1.0f / 1024.0f);
        float chi = c_hi;                 // exact count of z > hi (bisection invariant)

        // false-position estimate of the K-th order statistic inside [lo,hi]
        float Tk = lo + (hi - lo) * (c_lo - (float)KSEL)
                        * __fdividef(1.0f, fmaxf(c_lo - c_hi, 1.0f));
        Tk = fminf(fmaxf(Tk, lo), hi);

        float surp = (ssum + ((float)KSEL - chi) * Tk) * (1.0f / (float)KSEL);
        float gate = 1.0f + g_alpha * tanhf(g_sigma * surp);

        // ---- pass 2: out = gate * gelu (LDS + FMUL + STG only) ----
        #pragma unroll
        for (int c = 0; c < CHUNKS; c++) {
            float4 gv = swarp[c * 32];
            float4 o;
            o.x = gate * gv.x;
            o.y = gate * gv.y;
            o.z = gate * gv.z;
            o.w = gate * gv.w;
            orow[c * 32] = o;
        }
    }
}

extern "C" void kernel_launch(void* const* d_in, const int* in_sizes, int n_in,
                              void* d_out, int out_size) {
    const float* x         = (const float*)d_in[0];
    const float* log_alpha = (const float*)d_in[1];
    const float* log_sigma = (const float*)d_in[2];
    const float* ema_mean  = (const float*)d_in[3];
    const float* ema_sq    = (const float*)d_in[4];
    float* out = (float*)d_out;

    int d    = in_sizes[3];          // 1024
    int rows = in_sizes[0] / d;      // 32768

    prep_kernel<<<(d + 255) / 256, 256>>>(ema_mean, ema_sq, log_alpha, log_sigma, d);

    int blocks = (rows + WPB - 1) / WPB;    // 8 warps (rows) per 256-thread block
    gelu_topk_kernel<<<blocks, 256>>>(
        reinterpret_cast<const float4*>(x),
        reinterpret_cast<float4*>(out), rows);
}